// round 17
// baseline (speedup 1.0000x reference)
#include <cuda_runtime.h>
#include <cuda_bf16.h>
#include <math.h>

// WarpTranspose: adjoint of bilinear warp (flow-guided bilinear scatter-add).
// grad_out: [B,H,W,C] f32, u: [B,H,W,2] f32 (dx,dy), out: [B,H,W,C] f32.
//
// Graph-forked pipeline: zero(image i) runs on a side stream, scatter(image i)
// on the main stream waits on it via an event edge. All valid scatter targets
// of image i lie inside image i (out-of-image corners get zero weight), so the
// per-image dependency is exact. Scatter nodes serialize with each other
// (atomic-pipe floor: 16 RED lane-ops/px x ~0.854 cyc ~= 95us); zeroing of
// later images overlaps earlier scatters on free SM slots.

#define H_DIM 512
#define W_DIM 512
#define C_DIM 16
#define HW    (H_DIM * W_DIM)

// ---------------- per-image zero: 16.8MB, one float4 store per thread -------
__global__ void __launch_bounds__(256)
zero_img(float4* __restrict__ out4) {
    unsigned long long pol_last;
    asm("createpolicy.fractional.L2::evict_last.b64 %0, 1.0;" : "=l"(pol_last));
    float4* p = out4 + (size_t)blockIdx.x * 256 + threadIdx.x;
    asm volatile("st.global.L2::cache_hint.v4.f32 [%0], {%1, %2, %3, %4}, %5;"
                 :: "l"(p), "f"(0.f), "f"(0.f), "f"(0.f), "f"(0.f),
                    "l"(pol_last) : "memory");
}

// ---------------- per-image scatter (R1 mapping, at RED floor) --------------
__global__ void __launch_bounds__(256)
warp_transpose_scatter(const float* __restrict__ grad_out,
                       const float* __restrict__ u,
                       float* __restrict__ out,
                       int img) {
    unsigned long long pol_first;
    asm("createpolicy.fractional.L2::evict_first.b64 %0, 1.0;" : "=l"(pol_first));

    const int gid = blockIdx.x * 256 + threadIdx.x;   // exact grid: no guard
    const int quad = gid & 3;                         // float4 of 16 channels
    const int lp   = gid >> 2;                        // pixel within image
    const size_t p = (size_t)img * HW + lp;           // global pixel

    const int x = lp & (W_DIM - 1);
    const int y = (lp >> 9) & (H_DIM - 1);

    float ux, uy;
    asm volatile("ld.global.nc.L2::cache_hint.v2.f32 {%0, %1}, [%2], %3;"
                 : "=f"(ux), "=f"(uy)
                 : "l"(u + 2 * p), "l"(pol_first));
    float4 g;
    asm volatile("ld.global.nc.L2::cache_hint.v4.f32 {%0, %1, %2, %3}, [%4], %5;"
                 : "=f"(g.x), "=f"(g.y), "=f"(g.z), "=f"(g.w)
                 : "l"(grad_out + p * C_DIM + quad * 4), "l"(pol_first));

    const float gx = (float)x + ux;
    const float gy = (float)y + uy;

    const float x0f = floorf(gx);
    const float y0f = floorf(gy);
    const float wx = gx - x0f;
    const float wy = gy - y0f;
    const int x0 = (int)x0f;
    const int y0 = (int)y0f;

    const bool vx0 = ((unsigned)x0 < (unsigned)W_DIM);
    const bool vx1 = ((unsigned)(x0 + 1) < (unsigned)W_DIM);
    const bool vy0 = ((unsigned)y0 < (unsigned)H_DIM);
    const bool vy1 = ((unsigned)(y0 + 1) < (unsigned)H_DIM);

    const float w00 = (1.0f - wy) * (1.0f - wx);
    const float w01 = (1.0f - wy) * wx;
    const float w10 = wy * (1.0f - wx);
    const float w11 = wy * wx;

    const int dy0 = (y0 - y) * W_DIM;
    const int dy1 = dy0 + W_DIM;
    const int dx0 = x0 - x;
    float* outq = out + p * C_DIM + quad * 4;

    if (vy0 & vx0) {
        float4 v = make_float4(g.x * w00, g.y * w00, g.z * w00, g.w * w00);
        atomicAdd((float4*)(outq + (long long)(dy0 + dx0) * C_DIM), v);
    }
    if (vy0 & vx1) {
        float4 v = make_float4(g.x * w01, g.y * w01, g.z * w01, g.w * w01);
        atomicAdd((float4*)(outq + (long long)(dy0 + dx0 + 1) * C_DIM), v);
    }
    if (vy1 & vx0) {
        float4 v = make_float4(g.x * w10, g.y * w10, g.z * w10, g.w * w10);
        atomicAdd((float4*)(outq + (long long)(dy1 + dx0) * C_DIM), v);
    }
    if (vy1 & vx1) {
        float4 v = make_float4(g.x * w11, g.y * w11, g.z * w11, g.w * w11);
        atomicAdd((float4*)(outq + (long long)(dy1 + dx0 + 1) * C_DIM), v);
    }
}

extern "C" void kernel_launch(void* const* d_in, const int* in_sizes, int n_in,
                              void* d_out, int out_size) {
    const float* grad_out = (const float*)d_in[0];
    const float* u        = (const float*)d_in[1];
    float* out = (float*)d_out;

    const int B = in_sizes[1] / (HW * 2);

    const int f4_per_img    = HW * C_DIM / 4;   // 1,048,576 float4
    const int zero_blocks   = f4_per_img / 256; // 4096
    const int quads_per_img = HW * 4;           // 1,048,576
    const int scat_blocks   = quads_per_img / 256; // 4096

    // Fork a side stream for the zero branch (host-side objects only; created
    // fresh each call, left alive — destroying mid-capture is illegal and they
    // hold no tracked device memory).
    cudaStream_t zs;
    cudaStreamCreateWithFlags(&zs, cudaStreamNonBlocking);
    cudaEvent_t fork;
    cudaEventCreateWithFlags(&fork, cudaEventDisableTiming);
    cudaEventRecord(fork, 0);
    cudaStreamWaitEvent(zs, fork, 0);

    for (int i = 0; i < B; i++) {
        zero_img<<<zero_blocks, 256, 0, zs>>>(
            (float4*)out + (size_t)i * f4_per_img);

        cudaEvent_t ez;
        cudaEventCreateWithFlags(&ez, cudaEventDisableTiming);
        cudaEventRecord(ez, zs);
        cudaStreamWaitEvent(0, ez, 0);          // join into main stream

        warp_transpose_scatter<<<scat_blocks, 256, 0, 0>>>(grad_out, u, out, i);
    }
    // Main stream's last scatter waits on the last zero event, so the side
    // branch is fully joined into the capture.
}